// round 8
// baseline (speedup 1.0000x reference)
#include <cuda_runtime.h>
#include <cuda_bf16.h>
#include <cstdint>

#define NNODES 10000
#define FDIM   256
#define NEDGES 320000

// -------- scratch (device globals; no allocation allowed) --------
__device__ float g_H1[NNODES * FDIM];
__device__ float g_H2[NNODES * FDIM];
__device__ float g_H3[NNODES * FDIM];
__device__ int   g_cnt[NNODES];
__device__ int   g_offs[NNODES + 1];
__device__ int   g_cur[NNODES];
__device__ int2  g_edge[NEDGES];       // interleaved {src, val-as-int}

// -------- persistent-kernel coordination --------
__device__ int          g_barCount;    // self-resetting
__device__ volatile int g_barSense;    // read-at-entry makes parity replay-safe
__device__ int          g_workCtr;     // zeroed each launch (phase 0)
__device__ volatile int g_scanEpoch;   // monotonic across launches

// ============================================================================
// smem layout (GEMM staging; 71680 B dynamic)
// ============================================================================
#define A_STRIDE 72
#define B_STRIDE 136
#define SM_AH 0
#define SM_AL (SM_AH + 128 * A_STRIDE * 2)
#define SM_BH (SM_AL + 128 * A_STRIDE * 2)
#define SM_BL (SM_BH + 64 * B_STRIDE * 2)
#define SM_GEMM_TOTAL (SM_BL + 64 * B_STRIDE * 2)  // 71680

__device__ __forceinline__ uint32_t smem_u32(const void* p) {
    uint32_t a;
    asm("{ .reg .u64 t; cvta.to.shared.u64 t, %1; cvt.u32.u64 %0, t; }"
        : "=r"(a) : "l"(p));
    return a;
}

__device__ __forceinline__ void ldsm_x4(uint32_t* r, uint32_t addr) {
    asm volatile("ldmatrix.sync.aligned.m8n8.x4.shared.b16 {%0,%1,%2,%3}, [%4];"
                 : "=r"(r[0]), "=r"(r[1]), "=r"(r[2]), "=r"(r[3]) : "r"(addr));
}
__device__ __forceinline__ void ldsm_x4_t(uint32_t* r, uint32_t addr) {
    asm volatile("ldmatrix.sync.aligned.m8n8.x4.trans.shared.b16 {%0,%1,%2,%3}, [%4];"
                 : "=r"(r[0]), "=r"(r[1]), "=r"(r[2]), "=r"(r[3]) : "r"(addr));
}
__device__ __forceinline__ void mma_bf16(float* d, const uint32_t* a, const uint32_t* b) {
    asm volatile(
        "mma.sync.aligned.m16n8k16.row.col.f32.bf16.bf16.f32 "
        "{%0,%1,%2,%3}, {%4,%5,%6,%7}, {%8,%9}, {%0,%1,%2,%3};"
        : "+f"(d[0]), "+f"(d[1]), "+f"(d[2]), "+f"(d[3])
        : "r"(a[0]), "r"(a[1]), "r"(a[2]), "r"(a[3]), "r"(b[0]), "r"(b[1]));
}

__device__ __forceinline__ uint32_t pack_hi(float x, float y) {
    __nv_bfloat16 hx = __float2bfloat16_rn(x);
    __nv_bfloat16 hy = __float2bfloat16_rn(y);
    return (uint32_t)__bfloat16_as_ushort(hx) | ((uint32_t)__bfloat16_as_ushort(hy) << 16);
}
__device__ __forceinline__ uint32_t pack_lo(float x, float y) {
    __nv_bfloat16 hx = __float2bfloat16_rn(x);
    __nv_bfloat16 hy = __float2bfloat16_rn(y);
    __nv_bfloat16 lx = __float2bfloat16_rn(x - __bfloat162float(hx));
    __nv_bfloat16 ly = __float2bfloat16_rn(y - __bfloat162float(hy));
    return (uint32_t)__bfloat16_as_ushort(lx) | ((uint32_t)__bfloat16_as_ushort(ly) << 16);
}

// ============================================================================
// Grid barrier (sense-reversing; safe because all CTAs are resident)
// ============================================================================
__device__ __forceinline__ void gridbar(int nCTA, int& sense)
{
    sense ^= 1;
    __threadfence();
    __syncthreads();
    if (threadIdx.x == 0) {
        if (atomicAdd(&g_barCount, 1) == nCTA - 1) {
            atomicExch(&g_barCount, 0);
            __threadfence();
            g_barSense = sense;
        } else {
            while (g_barSense != sense) { }
        }
        __threadfence();
    }
    __syncthreads();
}

// ============================================================================
// One 128x128 GEMM tile of C = X @ W (bf16 split 3-pass). CTA-wide.
// ============================================================================
__device__ void gemm_tile(const float* __restrict__ X, const float* __restrict__ W,
                          float* __restrict__ C, int M, int bm, int n0,
                          char* smem, uint32_t sb)
{
    const int tid = threadIdx.x;
    const int wid = tid >> 5;
    const int lane = tid & 31;
    const int wm = wid & 3;
    const int wn = wid >> 2;

    float acc[2][8][4];
    #pragma unroll
    for (int i = 0; i < 2; ++i)
        #pragma unroll
        for (int j = 0; j < 8; ++j)
            #pragma unroll
            for (int k = 0; k < 4; ++k) acc[i][j][k] = 0.f;

    const int l8 = lane & 7, lg = lane >> 3;
    const int a_row_off = l8 + (lg & 1) * 8;
    const int a_col_off = (lg >> 1) * 8;
    const int b_k_off = (lg & 1) * 8 + l8;
    const int b_n_off = (lg >> 1) * 8;

    for (int ch = 0; ch < 4; ++ch) {
        const int k0 = ch * 64;

        #pragma unroll
        for (int it = 0; it < 8; ++it) {
            int idx = tid + it * 256;
            int row = idx >> 4;
            int col = (idx & 15) << 2;
            float4 v = make_float4(0.f, 0.f, 0.f, 0.f);
            if (bm + row < M)
                v = *reinterpret_cast<const float4*>(X + (size_t)(bm + row) * 256 + k0 + col);
            uint32_t off = (uint32_t)(row * A_STRIDE + col) * 2;
            *reinterpret_cast<uint2*>(smem + SM_AH + off) =
                make_uint2(pack_hi(v.x, v.y), pack_hi(v.z, v.w));
            *reinterpret_cast<uint2*>(smem + SM_AL + off) =
                make_uint2(pack_lo(v.x, v.y), pack_lo(v.z, v.w));
        }
        #pragma unroll
        for (int it = 0; it < 8; ++it) {
            int idx = tid + it * 256;
            int kr = idx >> 5;
            int nc = (idx & 31) << 2;
            float4 v = *reinterpret_cast<const float4*>(W + (size_t)(k0 + kr) * 256 + n0 + nc);
            uint32_t off = (uint32_t)(kr * B_STRIDE + nc) * 2;
            *reinterpret_cast<uint2*>(smem + SM_BH + off) =
                make_uint2(pack_hi(v.x, v.y), pack_hi(v.z, v.w));
            *reinterpret_cast<uint2*>(smem + SM_BL + off) =
                make_uint2(pack_lo(v.x, v.y), pack_lo(v.z, v.w));
        }
        __syncthreads();

        #pragma unroll
        for (int ks = 0; ks < 4; ++ks) {
            const int kk = ks * 16;
            uint32_t ah[2][4], al[2][4], bf[8][2];

            #pragma unroll
            for (int fm = 0; fm < 2; ++fm) {
                uint32_t row = (uint32_t)(wm * 32 + fm * 16 + a_row_off);
                uint32_t col = (uint32_t)(kk + a_col_off);
                uint32_t rel = (row * A_STRIDE + col) * 2;
                ldsm_x4(ah[fm], sb + SM_AH + rel);
                ldsm_x4(al[fm], sb + SM_AL + rel);
            }
            #pragma unroll
            for (int p = 0; p < 4; ++p) {
                uint32_t krow = (uint32_t)(kk + b_k_off);
                uint32_t ncol = (uint32_t)(wn * 64 + p * 16 + b_n_off);
                ldsm_x4_t(&bf[p * 2][0], sb + SM_BH + (krow * B_STRIDE + ncol) * 2);
            }
            #pragma unroll
            for (int fm = 0; fm < 2; ++fm)
                #pragma unroll
                for (int fn = 0; fn < 8; ++fn) mma_bf16(acc[fm][fn], ah[fm], bf[fn]);
            #pragma unroll
            for (int fm = 0; fm < 2; ++fm)
                #pragma unroll
                for (int fn = 0; fn < 8; ++fn) mma_bf16(acc[fm][fn], al[fm], bf[fn]);
            #pragma unroll
            for (int p = 0; p < 4; ++p) {
                uint32_t krow = (uint32_t)(kk + b_k_off);
                uint32_t ncol = (uint32_t)(wn * 64 + p * 16 + b_n_off);
                ldsm_x4_t(&bf[p * 2][0], sb + SM_BL + (krow * B_STRIDE + ncol) * 2);
            }
            #pragma unroll
            for (int fm = 0; fm < 2; ++fm)
                #pragma unroll
                for (int fn = 0; fn < 8; ++fn) mma_bf16(acc[fm][fn], ah[fm], bf[fn]);
        }
        __syncthreads();
    }

    const int qr = lane >> 2;
    const int qc = (lane & 3) * 2;
    #pragma unroll
    for (int fm = 0; fm < 2; ++fm) {
        int r0 = bm + wm * 32 + fm * 16 + qr;
        #pragma unroll
        for (int fn = 0; fn < 8; ++fn) {
            int cc = n0 + wn * 64 + fn * 8 + qc;
            if (r0 < M)
                *reinterpret_cast<float2*>(C + (size_t)r0 * 256 + cc) =
                    make_float2(acc[fm][fn][0], acc[fm][fn][1]);
            if (r0 + 8 < M)
                *reinterpret_cast<float2*>(C + (size_t)(r0 + 8) * 256 + cc) =
                    make_float2(acc[fm][fn][2], acc[fm][fn][3]);
        }
    }
}

// ============================================================================
// CSR scan (CTA 0 only, 256 threads)
// ============================================================================
__device__ void scan_csr(int M)
{
    __shared__ int wsum[8];
    const int tid = threadIdx.x;
    const int ipt = (M + 255) >> 8;
    const int base = tid * ipt;

    int sum = 0;
    for (int j = 0; j < ipt; ++j) {
        int i = base + j;
        if (i < M) sum += g_cnt[i];
    }
    int lane = tid & 31, wrp = tid >> 5;
    int s = sum;
    #pragma unroll
    for (int d = 1; d < 32; d <<= 1) {
        int o = __shfl_up_sync(0xffffffff, s, d);
        if (lane >= d) s += o;
    }
    if (lane == 31) wsum[wrp] = s;
    __syncthreads();
    if (wrp == 0 && lane < 8) {
        int ws = wsum[lane];
        #pragma unroll
        for (int d = 1; d < 8; d <<= 1) {
            int o = __shfl_up_sync(0xff, ws, d);
            if (lane >= d) ws += o;
        }
        wsum[lane] = ws;
    }
    __syncthreads();
    int run = ((wrp == 0) ? 0 : wsum[wrp - 1]) + (s - sum);
    for (int j = 0; j < ipt; ++j) {
        int i = base + j;
        if (i < M) {
            g_offs[i] = run;
            g_cur[i] = run;
            run += g_cnt[i];
        }
    }
    if (tid == 255) g_offs[M] = run;
}

// ============================================================================
// Scatter chunk: permute edges into dst-grouped runs (atomic positions)
// ============================================================================
__device__ void scatter_chunk(int c, int CH,
                              const int* __restrict__ src, const int* __restrict__ dst,
                              const float* __restrict__ vals, int E)
{
    const int tid = threadIdx.x;
    const int c0 = c * CH;
    const int cend = (c0 + CH < E) ? c0 + CH : E;
    for (int e = c0 + tid; e < cend; e += 256 * 4) {
        #pragma unroll
        for (int j = 0; j < 4; ++j) {
            int ee = e + j * 256;
            if (ee < cend) {
                int d = __ldg(dst + ee);
                int s = __ldg(src + ee);
                float v = __ldg(vals + ee);
                int pos = atomicAdd(&g_cur[d], 1);
                g_edge[pos] = make_int2(s, __float_as_int(v));
            }
        }
    }
}

// ============================================================================
// SpMM phase (all CTAs, static node striding). 64 threads/node.
// ============================================================================
__device__ void spmm_phase(const float* __restrict__ h, float* __restrict__ outp,
                           int M, int finalMode, int nCTA)
{
    const int tid = threadIdx.x;
    const int sub = tid >> 6;
    const int c = (tid & 63) << 2;

    for (int node = blockIdx.x * 4 + sub; node < M; node += nCTA * 4) {
        int beg = __ldg(g_offs + node);
        int end = __ldg(g_offs + node + 1);

        float4 acc;
        if (finalMode) acc = make_float4(0.f, 0.f, 0.f, 0.f);
        else           acc = *reinterpret_cast<const float4*>(outp + (size_t)node * FDIM + c);

        int e = beg;
        for (; e + 4 <= end; e += 4) {
            int2 e0 = __ldg(g_edge + e),     e1 = __ldg(g_edge + e + 1);
            int2 e2 = __ldg(g_edge + e + 2), e3 = __ldg(g_edge + e + 3);
            float v0 = __int_as_float(e0.y), v1 = __int_as_float(e1.y);
            float v2 = __int_as_float(e2.y), v3 = __int_as_float(e3.y);
            float4 r0 = *reinterpret_cast<const float4*>(h + (size_t)e0.x * FDIM + c);
            float4 r1 = *reinterpret_cast<const float4*>(h + (size_t)e1.x * FDIM + c);
            float4 r2 = *reinterpret_cast<const float4*>(h + (size_t)e2.x * FDIM + c);
            float4 r3 = *reinterpret_cast<const float4*>(h + (size_t)e3.x * FDIM + c);
            acc.x = fmaf(v0, r0.x, acc.x); acc.y = fmaf(v0, r0.y, acc.y);
            acc.z = fmaf(v0, r0.z, acc.z); acc.w = fmaf(v0, r0.w, acc.w);
            acc.x = fmaf(v1, r1.x, acc.x); acc.y = fmaf(v1, r1.y, acc.y);
            acc.z = fmaf(v1, r1.z, acc.z); acc.w = fmaf(v1, r1.w, acc.w);
            acc.x = fmaf(v2, r2.x, acc.x); acc.y = fmaf(v2, r2.y, acc.y);
            acc.z = fmaf(v2, r2.z, acc.z); acc.w = fmaf(v2, r2.w, acc.w);
            acc.x = fmaf(v3, r3.x, acc.x); acc.y = fmaf(v3, r3.y, acc.y);
            acc.z = fmaf(v3, r3.z, acc.z); acc.w = fmaf(v3, r3.w, acc.w);
        }
        for (; e < end; ++e) {
            int2 ed = __ldg(g_edge + e);
            float v = __int_as_float(ed.y);
            float4 r = *reinterpret_cast<const float4*>(h + (size_t)ed.x * FDIM + c);
            acc.x = fmaf(v, r.x, acc.x); acc.y = fmaf(v, r.y, acc.y);
            acc.z = fmaf(v, r.z, acc.z); acc.w = fmaf(v, r.w, acc.w);
        }

        if (finalMode) {
            const float third = 1.0f / 3.0f;
            acc.x = fmaxf(acc.x * third, 0.f);
            acc.y = fmaxf(acc.y * third, 0.f);
            acc.z = fmaxf(acc.z * third, 0.f);
            acc.w = fmaxf(acc.w * third, 0.f);
        }
        *reinterpret_cast<float4*>(outp + (size_t)node * FDIM + c) = acc;
    }
}

// ============================================================================
// Persistent mega-kernel:
//   zero -> bar -> hist -> bar -> [CTA0 scan || queue{GEMM tiles, scatter}]
//   -> bar -> SpMM1 -> bar -> SpMM2 -> bar -> SpMM3
// ============================================================================
__global__ __launch_bounds__(256, 2) void mega_kernel(
    const float* __restrict__ x, const float* __restrict__ A_vals,
    const float* __restrict__ W1, const float* __restrict__ W2, const float* __restrict__ W3,
    const int* __restrict__ e_src, const int* __restrict__ e_dst,
    float* __restrict__ out, int M, int E)
{
    extern __shared__ char smem[];
    __shared__ int s_item;
    const int tid = threadIdx.x;
    const int cta = blockIdx.x;
    const int nCTA = gridDim.x;

    int sense = g_barSense;            // replay-safe barrier parity
    const int epoch0 = g_scanEpoch;    // monotonic scan-done epoch

    // ---- P0: zero counters ----
    for (int i = cta * 256 + tid; i < M; i += nCTA * 256) g_cnt[i] = 0;
    if (cta == 0 && tid == 0) g_workCtr = 0;
    gridbar(nCTA, sense);

    // ---- P1: histogram of dst ----
    for (int e = cta * 256 + tid; e < E; e += nCTA * 256)
        atomicAdd(&g_cnt[__ldg(e_dst + e)], 1);
    gridbar(nCTA, sense);

    // ---- P2: CTA0 scans while everyone works the queue ----
    if (cta == 0) {
        scan_csr(M);
        __threadfence();
        __syncthreads();
        if (tid == 0) atomicAdd((int*)&g_scanEpoch, 1);
    }

    const int nTm = (M + 127) >> 7;        // 79 m-tiles
    const int nGemm = nTm * 6;             // 474 (3 weights x 2 n-halves)
    const int NSC = 32;                    // fat scatter chunks
    const int CH = (E + NSC - 1) / NSC;
    const int nItems = nGemm + NSC;
    const uint32_t sb = smem_u32(smem);

    for (;;) {
        __syncthreads();
        if (tid == 0) s_item = atomicAdd(&g_workCtr, 1);
        __syncthreads();
        const int item = s_item;
        if (item >= nItems) break;
        if (item < nGemm) {
            int m = item / 6, r = item - m * 6;
            int n0 = (r & 1) << 7;
            int w = r >> 1;
            const float* W = (w == 0) ? W1 : (w == 1) ? W2 : W3;
            float* C = (w == 0) ? g_H1 : (w == 1) ? g_H2 : g_H3;
            gemm_tile(x, W, C, M, m << 7, n0, smem, sb);
        } else {
            if (tid == 0) { while (g_scanEpoch == epoch0) { } }
            __syncthreads();
            scatter_chunk(item - nGemm, CH, e_src, e_dst, A_vals, E);
        }
    }
    gridbar(nCTA, sense);

    // ---- Horner SpMM chain ----
    spmm_phase(g_H3, g_H2, M, 0, nCTA);    // H2 += A H3
    gridbar(nCTA, sense);
    spmm_phase(g_H2, g_H1, M, 0, nCTA);    // H1 += A H2
    gridbar(nCTA, sense);
    spmm_phase(g_H1, out, M, 1, nCTA);     // out = relu(A H1 / 3)
}

// ============================================================================
extern "C" void kernel_launch(void* const* d_in, const int* in_sizes, int n_in,
                              void* d_out, int out_size)
{
    const float* x      = (const float*)d_in[0];
    const float* A_vals = (const float*)d_in[1];
    const float* W1     = (const float*)d_in[2];
    const float* W2     = (const float*)d_in[3];
    const float* W3     = (const float*)d_in[4];
    const int*   e_src  = (const int*)d_in[5];
    const int*   e_dst  = (const int*)d_in[6];
    float* out = (float*)d_out;

    const int M = in_sizes[0] / FDIM;      // 10000
    const int E = in_sizes[5];             // 320000

    int dev = 0;
    cudaGetDevice(&dev);
    int smCount = 0;
    cudaDeviceGetAttribute(&smCount, cudaDevAttrMultiProcessorCount, dev);
    const int nCTA = smCount * 2;          // exactly resident (launch_bounds(256,2))

    cudaFuncSetAttribute(mega_kernel, cudaFuncAttributeMaxDynamicSharedMemorySize,
                         SM_GEMM_TOTAL);
    mega_kernel<<<nCTA, 256, SM_GEMM_TOTAL>>>(x, A_vals, W1, W2, W3,
                                              e_src, e_dst, out, M, E);
}

// round 9
// speedup vs baseline: 1.1303x; 1.1303x over previous
#include <cuda_runtime.h>
#include <cuda_bf16.h>
#include <cstdint>

#define NNODES 10000
#define FDIM   256
#define NEDGES 320000

// -------- scratch (device globals; no allocation allowed) --------
__device__ float g_H1[NNODES * FDIM];
__device__ float g_H2[NNODES * FDIM];
__device__ float g_H3[NNODES * FDIM];
__device__ int   g_cnt[NNODES];
__device__ int   g_offs[NNODES + 1];
__device__ int   g_cur[NNODES];
__device__ int2  g_edge[NEDGES];       // interleaved {src, val-as-int}

// -------- persistent-kernel coordination --------
__device__ int          g_barCount;    // self-resetting
__device__ volatile int g_barSense;    // read-at-entry makes parity replay-safe
__device__ int          g_workCtr;     // zeroed each launch (phase 0)
__device__ volatile int g_scanEpoch;   // monotonic across launches

// ============================================================================
// smem layout (GEMM staging; 71680 B dynamic)
// ============================================================================
#define A_STRIDE 72
#define B_STRIDE 136
#define SM_AH 0
#define SM_AL (SM_AH + 128 * A_STRIDE * 2)
#define SM_BH (SM_AL + 128 * A_STRIDE * 2)
#define SM_BL (SM_BH + 64 * B_STRIDE * 2)
#define SM_GEMM_TOTAL (SM_BL + 64 * B_STRIDE * 2)  // 71680

__device__ __forceinline__ uint32_t smem_u32(const void* p) {
    uint32_t a;
    asm("{ .reg .u64 t; cvta.to.shared.u64 t, %1; cvt.u32.u64 %0, t; }"
        : "=r"(a) : "l"(p));
    return a;
}

__device__ __forceinline__ void ldsm_x4(uint32_t* r, uint32_t addr) {
    asm volatile("ldmatrix.sync.aligned.m8n8.x4.shared.b16 {%0,%1,%2,%3}, [%4];"
                 : "=r"(r[0]), "=r"(r[1]), "=r"(r[2]), "=r"(r[3]) : "r"(addr));
}
__device__ __forceinline__ void ldsm_x4_t(uint32_t* r, uint32_t addr) {
    asm volatile("ldmatrix.sync.aligned.m8n8.x4.trans.shared.b16 {%0,%1,%2,%3}, [%4];"
                 : "=r"(r[0]), "=r"(r[1]), "=r"(r[2]), "=r"(r[3]) : "r"(addr));
}
__device__ __forceinline__ void mma_bf16(float* d, const uint32_t* a, const uint32_t* b) {
    asm volatile(
        "mma.sync.aligned.m16n8k16.row.col.f32.bf16.bf16.f32 "
        "{%0,%1,%2,%3}, {%4,%5,%6,%7}, {%8,%9}, {%0,%1,%2,%3};"
        : "+f"(d[0]), "+f"(d[1]), "+f"(d[2]), "+f"(d[3])
        : "r"(a[0]), "r"(a[1]), "r"(a[2]), "r"(a[3]), "r"(b[0]), "r"(b[1]));
}

__device__ __forceinline__ uint32_t pack_hi(float x, float y) {
    __nv_bfloat16 hx = __float2bfloat16_rn(x);
    __nv_bfloat16 hy = __float2bfloat16_rn(y);
    return (uint32_t)__bfloat16_as_ushort(hx) | ((uint32_t)__bfloat16_as_ushort(hy) << 16);
}
__device__ __forceinline__ uint32_t pack_lo(float x, float y) {
    __nv_bfloat16 hx = __float2bfloat16_rn(x);
    __nv_bfloat16 hy = __float2bfloat16_rn(y);
    __nv_bfloat16 lx = __float2bfloat16_rn(x - __bfloat162float(hx));
    __nv_bfloat16 ly = __float2bfloat16_rn(y - __bfloat162float(hy));
    return (uint32_t)__bfloat16_as_ushort(lx) | ((uint32_t)__bfloat16_as_ushort(ly) << 16);
}

// ============================================================================
// Grid barrier (sense-reversing; safe because all CTAs are resident)
// ============================================================================
__device__ __forceinline__ void gridbar(int nCTA, int& sense)
{
    sense ^= 1;
    __threadfence();
    __syncthreads();
    if (threadIdx.x == 0) {
        if (atomicAdd(&g_barCount, 1) == nCTA - 1) {
            atomicExch(&g_barCount, 0);
            __threadfence();
            g_barSense = sense;
        } else {
            while (g_barSense != sense) { }
        }
        __threadfence();
    }
    __syncthreads();
}

// ============================================================================
// One 128x128 GEMM tile of C = X @ W (bf16 split 3-pass). CTA-wide.
// ============================================================================
__device__ void gemm_tile(const float* __restrict__ X, const float* __restrict__ W,
                          float* __restrict__ C, int M, int bm, int n0,
                          char* smem, uint32_t sb)
{
    const int tid = threadIdx.x;
    const int wid = tid >> 5;
    const int lane = tid & 31;
    const int wm = wid & 3;
    const int wn = wid >> 2;

    float acc[2][8][4];
    #pragma unroll
    for (int i = 0; i < 2; ++i)
        #pragma unroll
        for (int j = 0; j < 8; ++j)
            #pragma unroll
            for (int k = 0; k < 4; ++k) acc[i][j][k] = 0.f;

    const int l8 = lane & 7, lg = lane >> 3;
    const int a_row_off = l8 + (lg & 1) * 8;
    const int a_col_off = (lg >> 1) * 8;
    const int b_k_off = (lg & 1) * 8 + l8;
    const int b_n_off = (lg >> 1) * 8;

    for (int ch = 0; ch < 4; ++ch) {
        const int k0 = ch * 64;

        #pragma unroll
        for (int it = 0; it < 8; ++it) {
            int idx = tid + it * 256;
            int row = idx >> 4;
            int col = (idx & 15) << 2;
            float4 v = make_float4(0.f, 0.f, 0.f, 0.f);
            if (bm + row < M)
                v = *reinterpret_cast<const float4*>(X + (size_t)(bm + row) * 256 + k0 + col);
            uint32_t off = (uint32_t)(row * A_STRIDE + col) * 2;
            *reinterpret_cast<uint2*>(smem + SM_AH + off) =
                make_uint2(pack_hi(v.x, v.y), pack_hi(v.z, v.w));
            *reinterpret_cast<uint2*>(smem + SM_AL + off) =
                make_uint2(pack_lo(v.x, v.y), pack_lo(v.z, v.w));
        }
        #pragma unroll
        for (int it = 0; it < 8; ++it) {
            int idx = tid + it * 256;
            int kr = idx >> 5;
            int nc = (idx & 31) << 2;
            float4 v = *reinterpret_cast<const float4*>(W + (size_t)(k0 + kr) * 256 + n0 + nc);
            uint32_t off = (uint32_t)(kr * B_STRIDE + nc) * 2;
            *reinterpret_cast<uint2*>(smem + SM_BH + off) =
                make_uint2(pack_hi(v.x, v.y), pack_hi(v.z, v.w));
            *reinterpret_cast<uint2*>(smem + SM_BL + off) =
                make_uint2(pack_lo(v.x, v.y), pack_lo(v.z, v.w));
        }
        __syncthreads();

        #pragma unroll
        for (int ks = 0; ks < 4; ++ks) {
            const int kk = ks * 16;
            uint32_t ah[2][4], al[2][4], bf[8][2];

            #pragma unroll
            for (int fm = 0; fm < 2; ++fm) {
                uint32_t row = (uint32_t)(wm * 32 + fm * 16 + a_row_off);
                uint32_t col = (uint32_t)(kk + a_col_off);
                uint32_t rel = (row * A_STRIDE + col) * 2;
                ldsm_x4(ah[fm], sb + SM_AH + rel);
                ldsm_x4(al[fm], sb + SM_AL + rel);
            }
            #pragma unroll
            for (int p = 0; p < 4; ++p) {
                uint32_t krow = (uint32_t)(kk + b_k_off);
                uint32_t ncol = (uint32_t)(wn * 64 + p * 16 + b_n_off);
                ldsm_x4_t(&bf[p * 2][0], sb + SM_BH + (krow * B_STRIDE + ncol) * 2);
            }
            #pragma unroll
            for (int fm = 0; fm < 2; ++fm)
                #pragma unroll
                for (int fn = 0; fn < 8; ++fn) mma_bf16(acc[fm][fn], ah[fm], bf[fn]);
            #pragma unroll
            for (int fm = 0; fm < 2; ++fm)
                #pragma unroll
                for (int fn = 0; fn < 8; ++fn) mma_bf16(acc[fm][fn], al[fm], bf[fn]);
            #pragma unroll
            for (int p = 0; p < 4; ++p) {
                uint32_t krow = (uint32_t)(kk + b_k_off);
                uint32_t ncol = (uint32_t)(wn * 64 + p * 16 + b_n_off);
                ldsm_x4_t(&bf[p * 2][0], sb + SM_BL + (krow * B_STRIDE + ncol) * 2);
            }
            #pragma unroll
            for (int fm = 0; fm < 2; ++fm)
                #pragma unroll
                for (int fn = 0; fn < 8; ++fn) mma_bf16(acc[fm][fn], ah[fm], bf[fn]);
        }
        __syncthreads();
    }

    const int qr = lane >> 2;
    const int qc = (lane & 3) * 2;
    #pragma unroll
    for (int fm = 0; fm < 2; ++fm) {
        int r0 = bm + wm * 32 + fm * 16 + qr;
        #pragma unroll
        for (int fn = 0; fn < 8; ++fn) {
            int cc = n0 + wn * 64 + fn * 8 + qc;
            if (r0 < M)
                *reinterpret_cast<float2*>(C + (size_t)r0 * 256 + cc) =
                    make_float2(acc[fm][fn][0], acc[fm][fn][1]);
            if (r0 + 8 < M)
                *reinterpret_cast<float2*>(C + (size_t)(r0 + 8) * 256 + cc) =
                    make_float2(acc[fm][fn][2], acc[fm][fn][3]);
        }
    }
}

// ============================================================================
// CSR scan (CTA 0 only, 256 threads)
// ============================================================================
__device__ void scan_csr(int M)
{
    __shared__ int wsum[8];
    const int tid = threadIdx.x;
    const int ipt = (M + 255) >> 8;
    const int base = tid * ipt;

    int sum = 0;
    for (int j = 0; j < ipt; ++j) {
        int i = base + j;
        if (i < M) sum += g_cnt[i];
    }
    int lane = tid & 31, wrp = tid >> 5;
    int s = sum;
    #pragma unroll
    for (int d = 1; d < 32; d <<= 1) {
        int o = __shfl_up_sync(0xffffffff, s, d);
        if (lane >= d) s += o;
    }
    if (lane == 31) wsum[wrp] = s;
    __syncthreads();
    if (wrp == 0 && lane < 8) {
        int ws = wsum[lane];
        #pragma unroll
        for (int d = 1; d < 8; d <<= 1) {
            int o = __shfl_up_sync(0xff, ws, d);
            if (lane >= d) ws += o;
        }
        wsum[lane] = ws;
    }
    __syncthreads();
    int run = ((wrp == 0) ? 0 : wsum[wrp - 1]) + (s - sum);
    for (int j = 0; j < ipt; ++j) {
        int i = base + j;
        if (i < M) {
            g_offs[i] = run;
            g_cur[i] = run;
            run += g_cnt[i];
        }
    }
    if (tid == 255) g_offs[M] = run;
}

// ============================================================================
// Scatter chunk: permute edges into dst-grouped runs (atomic positions)
// ============================================================================
__device__ void scatter_chunk(int c, int CH,
                              const int* __restrict__ src, const int* __restrict__ dst,
                              const float* __restrict__ vals, int E)
{
    const int tid = threadIdx.x;
    const int c0 = c * CH;
    const int cend = (c0 + CH < E) ? c0 + CH : E;
    for (int e = c0 + tid; e < cend; e += 256 * 4) {
        #pragma unroll
        for (int j = 0; j < 4; ++j) {
            int ee = e + j * 256;
            if (ee < cend) {
                int d = __ldg(dst + ee);
                int s = __ldg(src + ee);
                float v = __ldg(vals + ee);
                int pos = atomicAdd(&g_cur[d], 1);
                g_edge[pos] = make_int2(s, __float_as_int(v));
            }
        }
    }
}

// ============================================================================
// Persistent build kernel (CSR + GEMM only; SpMM runs standalone at high occ):
//   zero -> bar -> hist -> bar -> [CTA0 scan || queue{474 GEMM tiles, 32 scatter chunks}]
// ============================================================================
__global__ __launch_bounds__(256, 2) void build_kernel(
    const float* __restrict__ x, const float* __restrict__ A_vals,
    const float* __restrict__ W1, const float* __restrict__ W2, const float* __restrict__ W3,
    const int* __restrict__ e_src, const int* __restrict__ e_dst,
    int M, int E)
{
    extern __shared__ char smem[];
    __shared__ int s_item;
    const int tid = threadIdx.x;
    const int cta = blockIdx.x;
    const int nCTA = gridDim.x;

    int sense = g_barSense;            // replay-safe barrier parity
    const int epoch0 = g_scanEpoch;    // monotonic scan-done epoch

    // ---- P0: zero counters ----
    for (int i = cta * 256 + tid; i < M; i += nCTA * 256) g_cnt[i] = 0;
    if (cta == 0 && tid == 0) g_workCtr = 0;
    gridbar(nCTA, sense);

    // ---- P1: histogram of dst ----
    for (int e = cta * 256 + tid; e < E; e += nCTA * 256)
        atomicAdd(&g_cnt[__ldg(e_dst + e)], 1);
    gridbar(nCTA, sense);

    // ---- P2: CTA0 scans while everyone works the queue ----
    if (cta == 0) {
        scan_csr(M);
        __threadfence();
        __syncthreads();
        if (tid == 0) atomicAdd((int*)&g_scanEpoch, 1);
    }

    const int nTm = (M + 127) >> 7;        // 79 m-tiles
    const int nGemm = nTm * 6;             // 474 (3 weights x 2 n-halves)
    const int NSC = 32;                    // fat scatter chunks
    const int CH = (E + NSC - 1) / NSC;
    const int nItems = nGemm + NSC;
    const uint32_t sb = smem_u32(smem);

    for (;;) {
        __syncthreads();
        if (tid == 0) s_item = atomicAdd(&g_workCtr, 1);
        __syncthreads();
        const int item = s_item;
        if (item >= nItems) break;
        if (item < nGemm) {
            int m = item / 6, r = item - m * 6;
            int n0 = (r & 1) << 7;
            int w = r >> 1;
            const float* W = (w == 0) ? W1 : (w == 1) ? W2 : W3;
            float* C = (w == 0) ? g_H1 : (w == 1) ? g_H2 : g_H3;
            gemm_tile(x, W, C, M, m << 7, n0, smem, sb);
        } else {
            if (tid == 0) { while (g_scanEpoch == epoch0) { } }
            __syncthreads();
            scatter_chunk(item - nGemm, CH, e_src, e_dst, A_vals, E);
        }
    }
}

// ============================================================================
// CSR SpMM gather (standalone launch -> full occupancy). 64 threads/node.
// mode 0: out[n] += sum val*h[src] ; mode 1: out[n] = relu(sum/3)
// ============================================================================
__global__ __launch_bounds__(256) void spmm_csr(
    const float* __restrict__ h, float* __restrict__ outp,
    const int2* __restrict__ edges, const int* __restrict__ offs, int M, int finalMode)
{
    int node = blockIdx.x * 4 + (threadIdx.x >> 6);
    if (node >= M) return;
    int c = (threadIdx.x & 63) << 2;

    int beg = __ldg(offs + node);
    int end = __ldg(offs + node + 1);

    float4 acc;
    if (finalMode) acc = make_float4(0.f, 0.f, 0.f, 0.f);
    else           acc = *reinterpret_cast<const float4*>(outp + (size_t)node * FDIM + c);

    int e = beg;
    for (; e + 4 <= end; e += 4) {
        int2 e0 = __ldg(edges + e),     e1 = __ldg(edges + e + 1);
        int2 e2 = __ldg(edges + e + 2), e3 = __ldg(edges + e + 3);
        float v0 = __int_as_float(e0.y), v1 = __int_as_float(e1.y);
        float v2 = __int_as_float(e2.y), v3 = __int_as_float(e3.y);
        float4 r0 = *reinterpret_cast<const float4*>(h + (size_t)e0.x * FDIM + c);
        float4 r1 = *reinterpret_cast<const float4*>(h + (size_t)e1.x * FDIM + c);
        float4 r2 = *reinterpret_cast<const float4*>(h + (size_t)e2.x * FDIM + c);
        float4 r3 = *reinterpret_cast<const float4*>(h + (size_t)e3.x * FDIM + c);
        acc.x = fmaf(v0, r0.x, acc.x); acc.y = fmaf(v0, r0.y, acc.y);
        acc.z = fmaf(v0, r0.z, acc.z); acc.w = fmaf(v0, r0.w, acc.w);
        acc.x = fmaf(v1, r1.x, acc.x); acc.y = fmaf(v1, r1.y, acc.y);
        acc.z = fmaf(v1, r1.z, acc.z); acc.w = fmaf(v1, r1.w, acc.w);
        acc.x = fmaf(v2, r2.x, acc.x); acc.y = fmaf(v2, r2.y, acc.y);
        acc.z = fmaf(v2, r2.z, acc.z); acc.w = fmaf(v2, r2.w, acc.w);
        acc.x = fmaf(v3, r3.x, acc.x); acc.y = fmaf(v3, r3.y, acc.y);
        acc.z = fmaf(v3, r3.z, acc.z); acc.w = fmaf(v3, r3.w, acc.w);
    }
    for (; e < end; ++e) {
        int2 ed = __ldg(edges + e);
        float v = __int_as_float(ed.y);
        float4 r = *reinterpret_cast<const float4*>(h + (size_t)ed.x * FDIM + c);
        acc.x = fmaf(v, r.x, acc.x); acc.y = fmaf(v, r.y, acc.y);
        acc.z = fmaf(v, r.z, acc.z); acc.w = fmaf(v, r.w, acc.w);
    }

    if (finalMode) {
        const float third = 1.0f / 3.0f;
        acc.x = fmaxf(acc.x * third, 0.f);
        acc.y = fmaxf(acc.y * third, 0.f);
        acc.z = fmaxf(acc.z * third, 0.f);
        acc.w = fmaxf(acc.w * third, 0.f);
    }
    *reinterpret_cast<float4*>(outp + (size_t)node * FDIM + c) = acc;
}

// ============================================================================
// out = relu( (1/3) * A*(h1 + A*(h2 + A*h3)) ),  hk = x @ Wk   (Horner)
// ============================================================================
extern "C" void kernel_launch(void* const* d_in, const int* in_sizes, int n_in,
                              void* d_out, int out_size)
{
    const float* x      = (const float*)d_in[0];
    const float* A_vals = (const float*)d_in[1];
    const float* W1     = (const float*)d_in[2];
    const float* W2     = (const float*)d_in[3];
    const float* W3     = (const float*)d_in[4];
    const int*   e_src  = (const int*)d_in[5];
    const int*   e_dst  = (const int*)d_in[6];
    float* out = (float*)d_out;

    const int M = in_sizes[0] / FDIM;      // 10000
    const int E = in_sizes[5];             // 320000

    float *H1, *H2, *H3; int *offs; int2 *edges;
    cudaGetSymbolAddress((void**)&H1, g_H1);
    cudaGetSymbolAddress((void**)&H2, g_H2);
    cudaGetSymbolAddress((void**)&H3, g_H3);
    cudaGetSymbolAddress((void**)&offs, g_offs);
    cudaGetSymbolAddress((void**)&edges, g_edge);

    int dev = 0;
    cudaGetDevice(&dev);
    int smCount = 0;
    cudaDeviceGetAttribute(&smCount, cudaDevAttrMultiProcessorCount, dev);
    const int nCTA = smCount * 2;          // exactly resident (launch_bounds(256,2))

    cudaFuncSetAttribute(build_kernel, cudaFuncAttributeMaxDynamicSharedMemorySize,
                         SM_GEMM_TOTAL);

    // ---- fused CSR build + projections (persistent, overlapped) ----
    build_kernel<<<nCTA, 256, SM_GEMM_TOTAL>>>(x, A_vals, W1, W2, W3,
                                               e_src, e_dst, M, E);

    // ---- Horner SpMM chain (standalone launches -> full occupancy) ----
    const int spmmBlocks = (M + 3) / 4;
    spmm_csr<<<spmmBlocks, 256>>>(H3, H2, edges, offs, M, 0);   // H2 += A H3
    spmm_csr<<<spmmBlocks, 256>>>(H2, H1, edges, offs, M, 0);   // H1 += A H2
    spmm_csr<<<spmmBlocks, 256>>>(H1, out, edges, offs, M, 1);  // out = relu(A H1 / 3)
}